// round 16
// baseline (speedup 1.0000x reference)
#include <cuda_runtime.h>
#include <cuda_fp16.h>

#define J 256
#define D 64
#define M_TILE 64
#define THREADS 128
#define GRID 444            // persistent, 3 CTAs/SM

#define OFF_XRAW 0          // 16 KB raw x tile
#define OFF_A    16384      // 8 KB fp16 A tile
#define OFF_DIAG 24576      // 256 B
#define SMEM_BYTES (OFF_DIAG + 256)

#define LN16 2.7725887222397811f
#define CEPS 6.25e-6f       // ratio * eps

__device__ __forceinline__ unsigned sw128(unsigned off) { return off ^ ((off >> 3) & 0x70u); }

__device__ __forceinline__ unsigned s2u(const void* p) {
    unsigned a;
    asm("{ .reg .u64 t; cvta.to.shared.u64 t, %1; cvt.u32.u64 %0, t; }" : "=r"(a) : "l"(p));
    return a;
}
__device__ __forceinline__ unsigned pk16(float a, float b) {
    __half2 t = __floats2half2_rn(a, b);
    return *reinterpret_cast<unsigned*>(&t);
}
__device__ __forceinline__ void ldm_x4(unsigned& r0, unsigned& r1, unsigned& r2, unsigned& r3,
                                       unsigned addr) {
    asm volatile("ldmatrix.sync.aligned.m8n8.x4.shared.b16 {%0,%1,%2,%3}, [%4];"
                 : "=r"(r0), "=r"(r1), "=r"(r2), "=r"(r3) : "r"(addr));
}
__device__ __forceinline__ void mma_f16(float* d, const unsigned* a, const unsigned* b) {
    asm volatile(
        "mma.sync.aligned.m16n8k16.row.col.f32.f16.f16.f32 "
        "{%0,%1,%2,%3}, {%4,%5,%6,%7}, {%8,%9}, {%0,%1,%2,%3};"
        : "+f"(d[0]), "+f"(d[1]), "+f"(d[2]), "+f"(d[3])
        : "r"(a[0]), "r"(a[1]), "r"(a[2]), "r"(a[3]), "r"(b[0]), "r"(b[1]));
}
__device__ __forceinline__ void cp16(unsigned dst, const void* src) {
    asm volatile("cp.async.cg.shared.global [%0], [%1], 16;" :: "r"(dst), "l"(src));
}

__global__ __launch_bounds__(THREADS, 3)
void performer_hmma(const float* __restrict__ x,
                    const float* __restrict__ proj,
                    float* __restrict__ out,
                    int n_tiles) {
    extern __shared__ char smem[];
    const unsigned sb = s2u(smem);
    float* sdiag = reinterpret_cast<float*>(smem + OFF_DIAG);
    const float* xraw = reinterpret_cast<const float*>(smem + OFF_XRAW);

    const int tid = threadIdx.x, lane = tid & 31, w = tid >> 5;
    const int wn = w;            // each of 4 warps owns 64 features

    const float NORM = 0.3535533905932738f;   // 64^-0.25, folded into B

    // ---- persistent B fragments: fp16(p*NORM), 8 nt x 4 ks x 2 = 64 regs ----
    unsigned bf[8][4][2];
    {
        const int n_lo = (wn << 6) + (lane >> 2);
        const int kfr  = 2 * (lane & 3);
        #pragma unroll
        for (int nt = 0; nt < 8; nt++) {
            const float* pr = proj + (size_t)(n_lo + nt * 8) * D;
            #pragma unroll
            for (int ks = 0; ks < 4; ks++) {
                #pragma unroll
                for (int h = 0; h < 2; h++) {
                    float a = pr[ks * 16 + h * 8 + kfr]     * NORM;
                    float b = pr[ks * 16 + h * 8 + kfr + 1] * NORM;
                    bf[nt][ks][h] = pk16(a, b);
                }
            }
        }
    }

    // ---- prefetch first tile's raw x (16 KB) ----
    int tile = blockIdx.x;
    if (tile < n_tiles) {
        const char* src = reinterpret_cast<const char*>(x + (size_t)tile * M_TILE * D);
        #pragma unroll
        for (int r = 0; r < 8; r++) {
            int i = tid + r * THREADS;           // 1024 x 16B
            cp16(sb + OFF_XRAW + i * 16, src + i * 16);
        }
        asm volatile("cp.async.commit_group;" ::: "memory");
    }

    while (tile < n_tiles) {
        const int m0 = tile * M_TILE;
        asm volatile("cp.async.wait_group 0;" ::: "memory");
        __syncthreads();   // xraw ready; previous compute done

        // ---- convert xraw -> A fp16 (sw128, 128B rows) + diag ----
        #pragma unroll
        for (int r = 0; r < 4; r++) {
            int i8 = tid + r * THREADS;          // 512 groups of 8 floats
            int t = i8 >> 3, g = i8 & 7;
            const float4* srcv = reinterpret_cast<const float4*>(xraw + t * D + g * 8);
            float4 v0 = srcv[0], v1 = srcv[1];
            float s = v0.x * v0.x + v0.y * v0.y + v0.z * v0.z + v0.w * v0.w
                    + v1.x * v1.x + v1.y * v1.y + v1.z * v1.z + v1.w * v1.w;
            unsigned h0 = pk16(v0.x, v0.y), h1 = pk16(v0.z, v0.w);
            unsigned h2 = pk16(v1.x, v1.y), h3 = pk16(v1.z, v1.w);
            unsigned off = sw128((unsigned)(t * 128 + g * 16));
            *reinterpret_cast<uint4*>(smem + OFF_A + off) = make_uint4(h0, h1, h2, h3);
            s += __shfl_xor_sync(0xFFFFFFFFu, s, 1);
            s += __shfl_xor_sync(0xFFFFFFFFu, s, 2);
            s += __shfl_xor_sync(0xFFFFFFFFu, s, 4);
            if ((tid & 7) == 0) sdiag[t] = 0.5f * s + LN16;
        }
        __syncthreads();   // A + diag visible; xraw consumed

        // ---- prefetch next tile while computing this one ----
        const int next = tile + GRID;
        if (next < n_tiles) {
            const char* src = reinterpret_cast<const char*>(x + (size_t)next * M_TILE * D);
            #pragma unroll
            for (int r = 0; r < 8; r++) {
                int i = tid + r * THREADS;
                cp16(sb + OFF_XRAW + i * 16, src + i * 16);
            }
            asm volatile("cp.async.commit_group;" ::: "memory");
        }

        // ---- compute: 4 m-tiles/warp; per mt: 4 ks x (1 ldm + 8 MMA) ----
        const int rl = lane & 15;
        const unsigned kh = ((unsigned)(lane >> 4)) << 4;
        #pragma unroll
        for (int mt = 0; mt < 4; mt++) {
            float d[8][4];
            #pragma unroll
            for (int nt = 0; nt < 8; nt++)
                #pragma unroll
                for (int q = 0; q < 4; q++) d[nt][q] = 0.f;

            const unsigned rowoff = (unsigned)((mt * 16 + rl) * 128) + kh;
            #pragma unroll
            for (int ks = 0; ks < 4; ks++) {
                unsigned swo = sw128(rowoff + (unsigned)ks * 32u);
                unsigned a[4];
                ldm_x4(a[0], a[1], a[2], a[3], sb + OFF_A + swo);
                #pragma unroll
                for (int nt = 0; nt < 8; nt++)
                    mma_f16(d[nt], a, bf[nt][ks]);
            }
            // epilogue: D frag rows r0=lane>>2, r0+8; cols 2*(lane&3)+{0,1}
            const int r0  = mt * 16 + (lane >> 2);
            const float dg0 = sdiag[r0], dg1 = sdiag[r0 + 8];   // 0.5||x||^2 + ln16
            const int cbase = (wn << 6) + 2 * (lane & 3);
            float* orow0 = out + (size_t)(m0 + r0) * J + cbase;
            float* orow1 = out + (size_t)(m0 + r0 + 8) * J + cbase;
            #pragma unroll
            for (int nt = 0; nt < 8; nt++) {
                float2 o0, o1;
                o0.x = __expf(d[nt][0] - dg0) + CEPS;
                o0.y = __expf(d[nt][1] - dg0) + CEPS;
                o1.x = __expf(d[nt][2] - dg1) + CEPS;
                o1.y = __expf(d[nt][3] - dg1) + CEPS;
                *reinterpret_cast<float2*>(orow0 + nt * 8) = o0;
                *reinterpret_cast<float2*>(orow1 + nt * 8) = o1;
            }
        }
        tile = next;
    }
}

extern "C" void kernel_launch(void* const* d_in, const int* in_sizes, int n_in,
                              void* d_out, int out_size) {
    const float* x    = (const float*)d_in[0];   // [2,16,4096,64] fp32
    const float* proj = (const float*)d_in[1];   // [256,64] fp32
    float* out        = (float*)d_out;           // [2,16,4096,256] fp32

    const int M = in_sizes[0] / D;               // 131072 tokens
    const int n_tiles = M / M_TILE;              // 2048
    const int grid = (n_tiles < GRID) ? n_tiles : GRID;

    cudaFuncSetAttribute(performer_hmma,
                         cudaFuncAttributeMaxDynamicSharedMemorySize, SMEM_BYTES);

    performer_hmma<<<grid, THREADS, SMEM_BYTES>>>(x, proj, out, n_tiles);
}

// round 17
// speedup vs baseline: 1.2795x; 1.2795x over previous
#include <cuda_runtime.h>
#include <cuda_fp16.h>

#define J 256
#define D 64
#define M_TILE 64
#define THREADS 128
#define GRID 296            // persistent, 2 CTAs/SM

#define OFF_XRAW 0          // 16 KB raw x tile
#define OFF_A    16384      // 8 KB fp16 A tile
#define OFF_DIAG 24576      // 256 B
#define SMEM_BYTES (OFF_DIAG + 256)

#define LN16 2.7725887222397811f
#define CEPS 6.25e-6f       // ratio * eps

__device__ __forceinline__ unsigned sw128(unsigned off) { return off ^ ((off >> 3) & 0x70u); }

__device__ __forceinline__ unsigned s2u(const void* p) {
    unsigned a;
    asm("{ .reg .u64 t; cvta.to.shared.u64 t, %1; cvt.u32.u64 %0, t; }" : "=r"(a) : "l"(p));
    return a;
}
__device__ __forceinline__ unsigned pk16(float a, float b) {
    __half2 t = __floats2half2_rn(a, b);
    return *reinterpret_cast<unsigned*>(&t);
}
__device__ __forceinline__ void ldm_x4(unsigned& r0, unsigned& r1, unsigned& r2, unsigned& r3,
                                       unsigned addr) {
    asm volatile("ldmatrix.sync.aligned.m8n8.x4.shared.b16 {%0,%1,%2,%3}, [%4];"
                 : "=r"(r0), "=r"(r1), "=r"(r2), "=r"(r3) : "r"(addr));
}
__device__ __forceinline__ void mma_f16(float* d, const unsigned* a, const unsigned* b) {
    asm volatile(
        "mma.sync.aligned.m16n8k16.row.col.f32.f16.f16.f32 "
        "{%0,%1,%2,%3}, {%4,%5,%6,%7}, {%8,%9}, {%0,%1,%2,%3};"
        : "+f"(d[0]), "+f"(d[1]), "+f"(d[2]), "+f"(d[3])
        : "r"(a[0]), "r"(a[1]), "r"(a[2]), "r"(a[3]), "r"(b[0]), "r"(b[1]));
}
__device__ __forceinline__ void cp16(unsigned dst, const void* src) {
    asm volatile("cp.async.cg.shared.global [%0], [%1], 16;" :: "r"(dst), "l"(src));
}

__global__ __launch_bounds__(THREADS, 2)
void performer_hmma(const float* __restrict__ x,
                    const float* __restrict__ proj,
                    float* __restrict__ out,
                    int n_tiles) {
    extern __shared__ char smem[];
    const unsigned sb = s2u(smem);
    float* sdiag = reinterpret_cast<float*>(smem + OFF_DIAG);
    const float* xraw = reinterpret_cast<const float*>(smem + OFF_XRAW);

    const int tid = threadIdx.x, lane = tid & 31, w = tid >> 5;
    const int wn = w;            // each of 4 warps owns 64 features

    const float NORM = 0.3535533905932738f;   // 64^-0.25, folded into B

    // ---- persistent B fragments: fp16(p*NORM), 8 nt x 4 ks x 2 = 64 regs ----
    unsigned bf[8][4][2];
    {
        const int n_lo = (wn << 6) + (lane >> 2);
        const int kfr  = 2 * (lane & 3);
        #pragma unroll
        for (int nt = 0; nt < 8; nt++) {
            const float* pr = proj + (size_t)(n_lo + nt * 8) * D;
            #pragma unroll
            for (int ks = 0; ks < 4; ks++) {
                #pragma unroll
                for (int h = 0; h < 2; h++) {
                    float a = pr[ks * 16 + h * 8 + kfr]     * NORM;
                    float b = pr[ks * 16 + h * 8 + kfr + 1] * NORM;
                    bf[nt][ks][h] = pk16(a, b);
                }
            }
        }
    }

    // ---- prefetch first tile's raw x (16 KB) ----
    int tile = blockIdx.x;
    if (tile < n_tiles) {
        const char* src = reinterpret_cast<const char*>(x + (size_t)tile * M_TILE * D);
        #pragma unroll
        for (int r = 0; r < 8; r++) {
            int i = tid + r * THREADS;           // 1024 x 16B
            cp16(sb + OFF_XRAW + i * 16, src + i * 16);
        }
        asm volatile("cp.async.commit_group;" ::: "memory");
    }

    while (tile < n_tiles) {
        const int m0 = tile * M_TILE;
        asm volatile("cp.async.wait_group 0;" ::: "memory");
        __syncthreads();   // xraw ready; previous compute done

        // ---- convert xraw -> A fp16 (sw128, 128B rows) + diag ----
        #pragma unroll
        for (int r = 0; r < 4; r++) {
            int i8 = tid + r * THREADS;          // 512 groups of 8 floats
            int t = i8 >> 3, g = i8 & 7;
            const float4* srcv = reinterpret_cast<const float4*>(xraw + t * D + g * 8);
            float4 v0 = srcv[0], v1 = srcv[1];
            float s = v0.x * v0.x + v0.y * v0.y + v0.z * v0.z + v0.w * v0.w
                    + v1.x * v1.x + v1.y * v1.y + v1.z * v1.z + v1.w * v1.w;
            unsigned h0 = pk16(v0.x, v0.y), h1 = pk16(v0.z, v0.w);
            unsigned h2 = pk16(v1.x, v1.y), h3 = pk16(v1.z, v1.w);
            unsigned off = sw128((unsigned)(t * 128 + g * 16));
            *reinterpret_cast<uint4*>(smem + OFF_A + off) = make_uint4(h0, h1, h2, h3);
            s += __shfl_xor_sync(0xFFFFFFFFu, s, 1);
            s += __shfl_xor_sync(0xFFFFFFFFu, s, 2);
            s += __shfl_xor_sync(0xFFFFFFFFu, s, 4);
            if ((tid & 7) == 0) sdiag[t] = 0.5f * s + LN16;
        }
        __syncthreads();   // A + diag visible; xraw consumed

        // ---- prefetch next tile while computing this one ----
        const int next = tile + GRID;
        if (next < n_tiles) {
            const char* src = reinterpret_cast<const char*>(x + (size_t)next * M_TILE * D);
            #pragma unroll
            for (int r = 0; r < 8; r++) {
                int i = tid + r * THREADS;
                cp16(sb + OFF_XRAW + i * 16, src + i * 16);
            }
            asm volatile("cp.async.commit_group;" ::: "memory");
        }

        // ---- compute: 4 m-tiles/warp; per mt: 4 ks x (1 ldm + 8 MMA) ----
        const int rl = lane & 15;
        const unsigned kh = ((unsigned)(lane >> 4)) << 4;
        #pragma unroll
        for (int mt = 0; mt < 4; mt++) {
            float d[8][4];
            #pragma unroll
            for (int nt = 0; nt < 8; nt++)
                #pragma unroll
                for (int q = 0; q < 4; q++) d[nt][q] = 0.f;

            const unsigned rowoff = (unsigned)((mt * 16 + rl) * 128) + kh;
            #pragma unroll
            for (int ks = 0; ks < 4; ks++) {
                unsigned swo = sw128(rowoff + (unsigned)ks * 32u);
                unsigned a[4];
                ldm_x4(a[0], a[1], a[2], a[3], sb + OFF_A + swo);
                #pragma unroll
                for (int nt = 0; nt < 8; nt++)
                    mma_f16(d[nt], a, bf[nt][ks]);
            }
            // epilogue: D frag rows r0=lane>>2, r0+8; cols 2*(lane&3)+{0,1}
            const int r0  = mt * 16 + (lane >> 2);
            const float dg0 = sdiag[r0], dg1 = sdiag[r0 + 8];   // 0.5||x||^2 + ln16
            const int cbase = (wn << 6) + 2 * (lane & 3);
            float* orow0 = out + (size_t)(m0 + r0) * J + cbase;
            float* orow1 = out + (size_t)(m0 + r0 + 8) * J + cbase;
            #pragma unroll
            for (int nt = 0; nt < 8; nt++) {
                float2 o0, o1;
                o0.x = __expf(d[nt][0] - dg0) + CEPS;
                o0.y = __expf(d[nt][1] - dg0) + CEPS;
                o1.x = __expf(d[nt][2] - dg1) + CEPS;
                o1.y = __expf(d[nt][3] - dg1) + CEPS;
                *reinterpret_cast<float2*>(orow0 + nt * 8) = o0;
                *reinterpret_cast<float2*>(orow1 + nt * 8) = o1;
            }
        }
        tile = next;
    }
}

extern "C" void kernel_launch(void* const* d_in, const int* in_sizes, int n_in,
                              void* d_out, int out_size) {
    const float* x    = (const float*)d_in[0];   // [2,16,4096,64] fp32
    const float* proj = (const float*)d_in[1];   // [256,64] fp32
    float* out        = (float*)d_out;           // [2,16,4096,256] fp32

    const int M = in_sizes[0] / D;               // 131072 tokens
    const int n_tiles = M / M_TILE;              // 2048
    const int grid = (n_tiles < GRID) ? n_tiles : GRID;

    cudaFuncSetAttribute(performer_hmma,
                         cudaFuncAttributeMaxDynamicSharedMemorySize, SMEM_BYTES);

    performer_hmma<<<grid, THREADS, SMEM_BYTES>>>(x, proj, out, n_tiles);
}